// round 10
// baseline (speedup 1.0000x reference)
#include <cuda_runtime.h>
#include <cstdint>

#define NLV 16
#define TSIZE (1u << 19)
#define HMASK (TSIZE - 1u)
#define PRIME1 2654435761u
#define PRIME2 805459861u

static __device__ __forceinline__ float2 lerp2(float2 a, float2 b, float w) {
    float u = 1.0f - w;
    return make_float2(a.x * u + b.x * w, a.y * u + b.y * w);
}

__global__ void __launch_bounds__(256)
hashenc_kernel(const float* __restrict__ x,
               const float2* __restrict__ emb,   // [16][2^19] float2
               const float* __restrict__ lw,     // [16]
               const float* __restrict__ bmin,   // [3]
               const float* __restrict__ bmax,   // [3]
               float* __restrict__ out,          // [N, 32]
               unsigned n)
{
    // floor(16 * b^i), b = exp((ln512 - ln16)/15) evaluated in float32 (numpy chain)
    const float RES[NLV] = {16.f, 20.f, 25.f, 32.f, 40.f, 50.f, 64.f, 80.f,
                            101.f, 128.f, 161.f, 203.f, 256.f, 322.f, 406.f, 512.f};

    __shared__ float sgate[NLV];
    __shared__ float srow[256][33];   // stride 33 -> conflict-free both phases
    if (threadIdx.x < NLV)
        sgate[threadIdx.x] = 1.0f / (1.0f + expf(-lw[threadIdx.x]));
    __syncthreads();

    unsigned tid = blockIdx.x * blockDim.x + threadIdx.x;
    bool active = (tid < n);

    float bm0 = __ldg(&bmin[0]), bm1 = __ldg(&bmin[1]), bm2 = __ldg(&bmin[2]);
    float bM0 = __ldg(&bmax[0]), bM1 = __ldg(&bmax[1]), bM2 = __ldg(&bmax[2]);

    if (active) {
        float x0 = x[3 * (size_t)tid + 0];
        float x1 = x[3 * (size_t)tid + 1];
        float x2 = x[3 * (size_t)tid + 2];

        float xc0 = fminf(fmaxf(x0, bm0), bM0);
        float xc1 = fminf(fmaxf(x1, bm1), bM1);
        float xc2 = fminf(fmaxf(x2, bm2), bM2);

#pragma unroll
        for (int l = 0; l < NLV; l++) {
            float res = RES[l];
            // grid = (box_max - box_min) / res  (per component)
            float g0 = (bM0 - bm0) / res;
            float g1 = (bM1 - bm1) / res;
            float g2 = (bM2 - bm2) / res;
            // bottom-left cell: floor((xc - box_min) / grid)
            float f0 = floorf((xc0 - bm0) / g0);
            float f1 = floorf((xc1 - bm1) / g1);
            float f2 = floorf((xc2 - bm2) / g2);
            // vmin / vmax, weights use raw x (matches reference)
            float v0 = f0 * g0 + bm0;
            float v1 = f1 * g1 + bm1;
            float v2 = f2 * g2 + bm2;
            float wx = (x0 - v0) / ((v0 + g0) - v0);
            float wy = (x1 - v1) / ((v1 + g1) - v1);
            float wz = (x2 - v2) / ((v2 + g2) - v2);

            unsigned b0 = (unsigned)(int)f0;
            unsigned b1 = (unsigned)(int)f1;
            unsigned b2 = (unsigned)(int)f2;

            unsigned hx0 = b0;                      // * PRIME0 (=1)
            unsigned hx1 = b0 + 1u;
            unsigned hy0 = b1 * PRIME1;
            unsigned hy1 = (b1 + 1u) * PRIME1;
            unsigned hz0 = b2 * PRIME2;
            unsigned hz1 = (b2 + 1u) * PRIME2;

            const float2* tb = emb + (size_t)l * TSIZE;

            // corner index c = i*4 + j*2 + k
            float2 e000 = __ldg(&tb[(hx0 ^ hy0 ^ hz0) & HMASK]);
            float2 e001 = __ldg(&tb[(hx0 ^ hy0 ^ hz1) & HMASK]);
            float2 e010 = __ldg(&tb[(hx0 ^ hy1 ^ hz0) & HMASK]);
            float2 e011 = __ldg(&tb[(hx0 ^ hy1 ^ hz1) & HMASK]);
            float2 e100 = __ldg(&tb[(hx1 ^ hy0 ^ hz0) & HMASK]);
            float2 e101 = __ldg(&tb[(hx1 ^ hy0 ^ hz1) & HMASK]);
            float2 e110 = __ldg(&tb[(hx1 ^ hy1 ^ hz0) & HMASK]);
            float2 e111 = __ldg(&tb[(hx1 ^ hy1 ^ hz1) & HMASK]);

            // trilinear: blend x, then y, then z (exact reference op order)
            float2 cx0 = lerp2(e000, e100, wx);
            float2 cx1 = lerp2(e001, e101, wx);
            float2 cx2 = lerp2(e010, e110, wx);
            float2 cx3 = lerp2(e011, e111, wx);
            float2 c0 = lerp2(cx0, cx2, wy);
            float2 c1 = lerp2(cx1, cx3, wy);
            float2 c  = lerp2(c0, c1, wz);

            float gate = sgate[l];
            srow[threadIdx.x][2 * l + 0] = c.x * gate;
            srow[threadIdx.x][2 * l + 1] = c.y * gate;
        }
    }
    __syncthreads();

    // warp-cooperative row writes: for each staged row, 32 lanes write 32
    // consecutive floats -> one 128B line -> 1 wavefront per row (vs 32 before)
    unsigned warp = threadIdx.x >> 5;
    unsigned lane = threadIdx.x & 31u;
    unsigned rowBase = warp * 32u;
    unsigned blockBase = blockIdx.x * 256u;
#pragma unroll
    for (unsigned r = 0; r < 32; r++) {
        unsigned localRow = rowBase + r;
        unsigned p = blockBase + localRow;
        if (p < n)
            out[(size_t)p * 32 + lane] = srow[localRow][lane];
    }
}

extern "C" void kernel_launch(void* const* d_in, const int* in_sizes, int n_in,
                              void* d_out, int out_size) {
    const float*  x    = (const float*)d_in[0];
    const float2* emb  = (const float2*)d_in[1];
    const float*  lw   = (const float*)d_in[2];
    const float*  bmin = (const float*)d_in[3];
    const float*  bmax = (const float*)d_in[4];
    float* out = (float*)d_out;

    unsigned n = (unsigned)(in_sizes[0] / 3);
    unsigned blocks = (n + 255) / 256;
    hashenc_kernel<<<blocks, 256>>>(x, emb, lw, bmin, bmax, out, n);
}

// round 12
// speedup vs baseline: 2.4592x; 2.4592x over previous
#include <cuda_runtime.h>
#include <cstdint>

#define NLV 16
#define TSIZE (1u << 19)
#define HMASK (TSIZE - 1u)
#define PRIME1 2654435761u
#define PRIME2 805459861u

#define BINRES 32
#define BINS 32768                    // 32^3 Morton bins
#define NSLOTS 2097152u               // BINS * 64
#define OVMAX 65536u

__device__ unsigned g_cnt[BINS];
__device__ unsigned g_over[1];
__device__ float4   g_xs[2097152];    // bucketed points, xyz + orig index in w (32MB)
__device__ float4   g_xso[65536];     // overflow (1MB)

static __device__ __forceinline__ float2 lerp2(float2 a, float2 b, float w) {
    float u = 1.0f - w;
    return make_float2(a.x * u + b.x * w, a.y * u + b.y * w);
}

// CORRECT 5-bit 3D Morton expand: b4..b0 -> bits 12,9,6,3,0  (verified)
static __device__ __forceinline__ unsigned expand_bits5(unsigned v) {
    v &= 0x1Fu;
    v = (v | (v << 8)) & 0x100Fu;   // b4 -> bit 12, b3..b0 stay 0..3
    v = (v | (v << 4)) & 0x10C3u;   // b3,b2 -> bits 7,6
    v = (v | (v << 2)) & 0x1249u;   // b3 -> 9, b1 -> 3
    return v;
}

static __device__ __forceinline__ unsigned point_bin(float x0, float x1, float x2,
                                                     float bm0, float bm1, float bm2,
                                                     float bM0, float bM1, float bM2) {
    float u0 = (fminf(fmaxf(x0, bm0), bM0) - bm0) / (bM0 - bm0);
    float u1 = (fminf(fmaxf(x1, bm1), bM1) - bm1) / (bM1 - bm1);
    float u2 = (fminf(fmaxf(x2, bm2), bM2) - bm2) / (bM2 - bm2);
    unsigned i0 = min((unsigned)(u0 * (float)BINRES), (unsigned)(BINRES - 1));
    unsigned i1 = min((unsigned)(u1 * (float)BINRES), (unsigned)(BINRES - 1));
    unsigned i2 = min((unsigned)(u2 * (float)BINRES), (unsigned)(BINRES - 1));
    return expand_bits5(i0) | (expand_bits5(i1) << 1) | (expand_bits5(i2) << 2);
}

static __device__ __forceinline__ void load4pts(const float4* __restrict__ x4,
                                                unsigned t, float px[4][3]) {
    float4 a0 = __ldg(&x4[3 * (size_t)t + 0]);
    float4 a1 = __ldg(&x4[3 * (size_t)t + 1]);
    float4 a2 = __ldg(&x4[3 * (size_t)t + 2]);
    px[0][0] = a0.x; px[0][1] = a0.y; px[0][2] = a0.z;
    px[1][0] = a0.w; px[1][1] = a1.x; px[1][2] = a1.y;
    px[2][0] = a1.z; px[2][1] = a1.w; px[2][2] = a2.x;
    px[3][0] = a2.y; px[3][1] = a2.z; px[3][2] = a2.w;
}

static __device__ __forceinline__ void deposit(float q0, float q1, float q2,
                                               unsigned idx,
                                               float bm0, float bm1, float bm2,
                                               float bM0, float bM1, float bM2) {
    unsigned b = point_bin(q0, q1, q2, bm0, bm1, bm2, bM0, bM1, bM2);
    unsigned c = atomicAdd(&g_cnt[b], 1u);
    float4 v = make_float4(q0, q1, q2, __uint_as_float(idx));
    if (c < 64u) {
        g_xs[b * 64u + c] = v;
    } else {
        unsigned k = atomicAdd(&g_over[0], 1u);
        if (k < OVMAX) g_xso[k] = v;
    }
}

__global__ void __launch_bounds__(256)
scatter_kernel(const float* __restrict__ x,
               const float* __restrict__ bmin,
               const float* __restrict__ bmax, unsigned n) {
    unsigned t = blockIdx.x * blockDim.x + threadIdx.x;
    unsigned base = t * 4u;
    if (base >= n) return;
    float bm0 = __ldg(&bmin[0]), bm1 = __ldg(&bmin[1]), bm2 = __ldg(&bmin[2]);
    float bM0 = __ldg(&bmax[0]), bM1 = __ldg(&bmax[1]), bM2 = __ldg(&bmax[2]);
    if (base + 4 <= n) {
        float px[4][3];
        load4pts((const float4*)x, t, px);
#pragma unroll
        for (int k = 0; k < 4; k++)
            deposit(px[k][0], px[k][1], px[k][2], base + k,
                    bm0, bm1, bm2, bM0, bM1, bM2);
    } else {
        for (unsigned i = base; i < n; i++) {
            float q0 = __ldg(&x[3 * (size_t)i + 0]);
            float q1 = __ldg(&x[3 * (size_t)i + 1]);
            float q2 = __ldg(&x[3 * (size_t)i + 2]);
            deposit(q0, q1, q2, i, bm0, bm1, bm2, bM0, bM1, bM2);
        }
    }
}

// all 16 levels on bucketed (Morton-sorted) points; direct row stores
__global__ void __launch_bounds__(256)
hashenc_kernel(const float2* __restrict__ emb,   // [16][2^19] float2
               const float* __restrict__ lw,     // [16]
               const float* __restrict__ bmin,   // [3]
               const float* __restrict__ bmax,   // [3]
               float* __restrict__ out)          // [N, 32]
{
    // floor(16 * b^i), b = exp((ln512 - ln16)/15) evaluated in float32 (numpy chain)
    const float RES[NLV] = {16.f, 20.f, 25.f, 32.f, 40.f, 50.f, 64.f, 80.f,
                            101.f, 128.f, 161.f, 203.f, 256.f, 322.f, 406.f, 512.f};

    unsigned j = blockIdx.x * blockDim.x + threadIdx.x;

    float4 xp;
    if (j < NSLOTS) {
        unsigned bin = j >> 6;
        unsigned slot = j & 63u;
        unsigned cnt = g_cnt[bin];
        if (slot >= min(cnt, 64u)) return;
        xp = g_xs[j];
    } else {
        unsigned k = j - NSLOTS;
        if (k >= min(g_over[0], OVMAX)) return;
        xp = g_xso[k];
    }

    unsigned p = __float_as_uint(xp.w);   // original point index (output row)
    float x0 = xp.x, x1 = xp.y, x2 = xp.z;

    float bm0 = __ldg(&bmin[0]), bm1 = __ldg(&bmin[1]), bm2 = __ldg(&bmin[2]);
    float bM0 = __ldg(&bmax[0]), bM1 = __ldg(&bmax[1]), bM2 = __ldg(&bmax[2]);

    float xc0 = fminf(fmaxf(x0, bm0), bM0);
    float xc1 = fminf(fmaxf(x1, bm1), bM1);
    float xc2 = fminf(fmaxf(x2, bm2), bM2);

    float o[2 * NLV];

#pragma unroll
    for (int l = 0; l < NLV; l++) {
        float res = RES[l];
        float g0 = (bM0 - bm0) / res;
        float g1 = (bM1 - bm1) / res;
        float g2 = (bM2 - bm2) / res;
        float f0 = floorf((xc0 - bm0) / g0);
        float f1 = floorf((xc1 - bm1) / g1);
        float f2 = floorf((xc2 - bm2) / g2);
        float v0 = f0 * g0 + bm0;
        float v1 = f1 * g1 + bm1;
        float v2 = f2 * g2 + bm2;
        float wx = (x0 - v0) / ((v0 + g0) - v0);
        float wy = (x1 - v1) / ((v1 + g1) - v1);
        float wz = (x2 - v2) / ((v2 + g2) - v2);

        unsigned b0 = (unsigned)(int)f0;
        unsigned b1 = (unsigned)(int)f1;
        unsigned b2 = (unsigned)(int)f2;

        unsigned hx0 = b0;                      // * PRIME0 (=1)
        unsigned hx1 = b0 + 1u;
        unsigned hy0 = b1 * PRIME1;
        unsigned hy1 = (b1 + 1u) * PRIME1;
        unsigned hz0 = b2 * PRIME2;
        unsigned hz1 = (b2 + 1u) * PRIME2;

        const float2* tb = emb + (size_t)l * TSIZE;

        // corner index c = i*4 + j*2 + k
        float2 e000 = __ldg(&tb[(hx0 ^ hy0 ^ hz0) & HMASK]);
        float2 e001 = __ldg(&tb[(hx0 ^ hy0 ^ hz1) & HMASK]);
        float2 e010 = __ldg(&tb[(hx0 ^ hy1 ^ hz0) & HMASK]);
        float2 e011 = __ldg(&tb[(hx0 ^ hy1 ^ hz1) & HMASK]);
        float2 e100 = __ldg(&tb[(hx1 ^ hy0 ^ hz0) & HMASK]);
        float2 e101 = __ldg(&tb[(hx1 ^ hy0 ^ hz1) & HMASK]);
        float2 e110 = __ldg(&tb[(hx1 ^ hy1 ^ hz0) & HMASK]);
        float2 e111 = __ldg(&tb[(hx1 ^ hy1 ^ hz1) & HMASK]);

        // trilinear: blend x, then y, then z (exact reference op order)
        float2 cx0 = lerp2(e000, e100, wx);
        float2 cx1 = lerp2(e001, e101, wx);
        float2 cx2 = lerp2(e010, e110, wx);
        float2 cx3 = lerp2(e011, e111, wx);
        float2 c0 = lerp2(cx0, cx2, wy);
        float2 c1 = lerp2(cx1, cx3, wy);
        float2 c  = lerp2(c0, c1, wz);

        float gate = 1.0f / (1.0f + expf(-__ldg(&lw[l])));
        o[2 * l + 0] = c.x * gate;
        o[2 * l + 1] = c.y * gate;
    }

    float4* o4 = reinterpret_cast<float4*>(out + (size_t)p * (2 * NLV));
#pragma unroll
    for (int q = 0; q < 8; q++)
        o4[q] = make_float4(o[4 * q + 0], o[4 * q + 1], o[4 * q + 2], o[4 * q + 3]);
}

extern "C" void kernel_launch(void* const* d_in, const int* in_sizes, int n_in,
                              void* d_out, int out_size) {
    const float*  x    = (const float*)d_in[0];
    const float2* emb  = (const float2*)d_in[1];
    const float*  lw   = (const float*)d_in[2];
    const float*  bmin = (const float*)d_in[3];
    const float*  bmax = (const float*)d_in[4];
    float* out = (float*)d_out;

    unsigned n = (unsigned)(in_sizes[0] / 3);
    unsigned t4 = (n + 3) / 4;

    void* cntPtr = nullptr;
    void* overPtr = nullptr;
    cudaGetSymbolAddress(&cntPtr, g_cnt);
    cudaGetSymbolAddress(&overPtr, g_over);
    cudaMemsetAsync(cntPtr, 0, BINS * sizeof(unsigned));
    cudaMemsetAsync(overPtr, 0, sizeof(unsigned));

    scatter_kernel<<<(t4 + 255) / 256, 256>>>(x, bmin, bmax, n);

    unsigned total = NSLOTS + OVMAX;
    hashenc_kernel<<<(total + 255) / 256, 256>>>(emb, lw, bmin, bmax, out);
}

// round 13
// speedup vs baseline: 2.8776x; 1.1702x over previous
#include <cuda_runtime.h>
#include <cstdint>

#define NLV 16
#define TSIZE (1u << 19)
#define HMASK (TSIZE - 1u)
#define PRIME1 2654435761u
#define PRIME2 805459861u

#define BINRES 32
#define BINS 32768                    // 32^3 Morton bins
#define NSLOTS 2097152u               // BINS * 64
#define OVMAX 65536u

__device__ unsigned g_cnt[BINS];
__device__ unsigned g_over[1];
__device__ float4   g_xs[2097152];    // bucketed points, xyz + orig index in w (32MB)
__device__ float4   g_xso[65536];     // overflow (1MB)

// floor(16 * b^i), b = exp((ln512 - ln16)/15) evaluated in float32 (numpy chain)
__device__ const float g_res[NLV] = {16.f, 20.f, 25.f, 32.f, 40.f, 50.f, 64.f, 80.f,
                                     101.f, 128.f, 161.f, 203.f, 256.f, 322.f, 406.f, 512.f};

static __device__ __forceinline__ float2 lerp2(float2 a, float2 b, float w) {
    float u = 1.0f - w;
    return make_float2(a.x * u + b.x * w, a.y * u + b.y * w);
}

// 5-bit 3D Morton expand: b4..b0 -> bits 12,9,6,3,0
static __device__ __forceinline__ unsigned expand_bits5(unsigned v) {
    v &= 0x1Fu;
    v = (v | (v << 8)) & 0x100Fu;
    v = (v | (v << 4)) & 0x10C3u;
    v = (v | (v << 2)) & 0x1249u;
    return v;
}

static __device__ __forceinline__ unsigned point_bin(float x0, float x1, float x2,
                                                     float bm0, float bm1, float bm2,
                                                     float bM0, float bM1, float bM2) {
    float u0 = (fminf(fmaxf(x0, bm0), bM0) - bm0) / (bM0 - bm0);
    float u1 = (fminf(fmaxf(x1, bm1), bM1) - bm1) / (bM1 - bm1);
    float u2 = (fminf(fmaxf(x2, bm2), bM2) - bm2) / (bM2 - bm2);
    unsigned i0 = min((unsigned)(u0 * (float)BINRES), (unsigned)(BINRES - 1));
    unsigned i1 = min((unsigned)(u1 * (float)BINRES), (unsigned)(BINRES - 1));
    unsigned i2 = min((unsigned)(u2 * (float)BINRES), (unsigned)(BINRES - 1));
    return expand_bits5(i0) | (expand_bits5(i1) << 1) | (expand_bits5(i2) << 2);
}

static __device__ __forceinline__ void load4pts(const float4* __restrict__ x4,
                                                unsigned t, float px[4][3]) {
    float4 a0 = __ldg(&x4[3 * (size_t)t + 0]);
    float4 a1 = __ldg(&x4[3 * (size_t)t + 1]);
    float4 a2 = __ldg(&x4[3 * (size_t)t + 2]);
    px[0][0] = a0.x; px[0][1] = a0.y; px[0][2] = a0.z;
    px[1][0] = a0.w; px[1][1] = a1.x; px[1][2] = a1.y;
    px[2][0] = a1.z; px[2][1] = a1.w; px[2][2] = a2.x;
    px[3][0] = a2.y; px[3][1] = a2.z; px[3][2] = a2.w;
}

static __device__ __forceinline__ void deposit(float q0, float q1, float q2,
                                               unsigned idx,
                                               float bm0, float bm1, float bm2,
                                               float bM0, float bM1, float bM2) {
    unsigned b = point_bin(q0, q1, q2, bm0, bm1, bm2, bM0, bM1, bM2);
    unsigned c = atomicAdd(&g_cnt[b], 1u);
    float4 v = make_float4(q0, q1, q2, __uint_as_float(idx));
    if (c < 64u) {
        g_xs[b * 64u + c] = v;
    } else {
        unsigned k = atomicAdd(&g_over[0], 1u);
        if (k < OVMAX) g_xso[k] = v;
    }
}

__global__ void __launch_bounds__(256)
scatter_kernel(const float* __restrict__ x,
               const float* __restrict__ bmin,
               const float* __restrict__ bmax, unsigned n) {
    unsigned t = blockIdx.x * blockDim.x + threadIdx.x;
    unsigned base = t * 4u;
    if (base >= n) return;
    float bm0 = __ldg(&bmin[0]), bm1 = __ldg(&bmin[1]), bm2 = __ldg(&bmin[2]);
    float bM0 = __ldg(&bmax[0]), bM1 = __ldg(&bmax[1]), bM2 = __ldg(&bmax[2]);
    if (base + 4 <= n) {
        float px[4][3];
        load4pts((const float4*)x, t, px);
#pragma unroll
        for (int k = 0; k < 4; k++)
            deposit(px[k][0], px[k][1], px[k][2], base + k,
                    bm0, bm1, bm2, bM0, bM1, bM2);
    } else {
        for (unsigned i = base; i < n; i++) {
            float q0 = __ldg(&x[3 * (size_t)i + 0]);
            float q1 = __ldg(&x[3 * (size_t)i + 1]);
            float q2 = __ldg(&x[3 * (size_t)i + 2]);
            deposit(q0, q1, q2, i, bm0, bm1, bm2, bM0, bM1, bM2);
        }
    }
}

// all 16 levels on bucketed (Morton-sorted) points; direct row stores
__global__ void __launch_bounds__(256)
hashenc_kernel(const float2* __restrict__ emb,   // [16][2^19] float2
               const float* __restrict__ lw,     // [16]
               const float* __restrict__ bmin,   // [3]
               const float* __restrict__ bmax,   // [3]
               float* __restrict__ out)          // [N, 32]
{
    // per-level constants, computed once per block (bit-exact same ops as reference)
    __shared__ float sg0[NLV], sg1[NLV], sg2[NLV];       // grid components
    __shared__ float sr0[NLV], sr1[NLV], sr2[NLV];       // reciprocals (for floor)
    __shared__ float sgate[NLV];
    if (threadIdx.x < NLV) {
        int l = threadIdx.x;
        float res = g_res[l];
        float bm0 = __ldg(&bmin[0]), bm1 = __ldg(&bmin[1]), bm2 = __ldg(&bmin[2]);
        float bM0 = __ldg(&bmax[0]), bM1 = __ldg(&bmax[1]), bM2 = __ldg(&bmax[2]);
        float g0 = (bM0 - bm0) / res;
        float g1 = (bM1 - bm1) / res;
        float g2 = (bM2 - bm2) / res;
        sg0[l] = g0; sg1[l] = g1; sg2[l] = g2;
        sr0[l] = 1.0f / g0; sr1[l] = 1.0f / g1; sr2[l] = 1.0f / g2;
        sgate[l] = 1.0f / (1.0f + expf(-lw[l]));
    }
    __syncthreads();

    unsigned j = blockIdx.x * blockDim.x + threadIdx.x;

    float4 xp;
    if (j < NSLOTS) {
        unsigned bin = j >> 6;
        unsigned slot = j & 63u;
        unsigned cnt = g_cnt[bin];
        if (slot >= min(cnt, 64u)) return;
        xp = g_xs[j];
    } else {
        unsigned k = j - NSLOTS;
        if (k >= min(g_over[0], OVMAX)) return;
        xp = g_xso[k];
    }

    unsigned p = __float_as_uint(xp.w);   // original point index (output row)
    float x0 = xp.x, x1 = xp.y, x2 = xp.z;

    float bm0 = __ldg(&bmin[0]), bm1 = __ldg(&bmin[1]), bm2 = __ldg(&bmin[2]);
    float bM0 = __ldg(&bmax[0]), bM1 = __ldg(&bmax[1]), bM2 = __ldg(&bmax[2]);

    float xc0 = fminf(fmaxf(x0, bm0), bM0);
    float xc1 = fminf(fmaxf(x1, bm1), bM1);
    float xc2 = fminf(fmaxf(x2, bm2), bM2);

    float o[2 * NLV];

#pragma unroll
    for (int l = 0; l < NLV; l++) {
        float g0 = sg0[l], g1 = sg1[l], g2 = sg2[l];
        // floor((xc-bm)/g) via precomputed reciprocal (value-safe: cell-boundary
        // flips land on shared faces where the trilinear blend is continuous)
        float f0 = floorf((xc0 - bm0) * sr0[l]);
        float f1 = floorf((xc1 - bm1) * sr1[l]);
        float f2 = floorf((xc2 - bm2) * sr2[l]);
        float v0 = f0 * g0 + bm0;
        float v1 = f1 * g1 + bm1;
        float v2 = f2 * g2 + bm2;
        float wx = (x0 - v0) / ((v0 + g0) - v0);
        float wy = (x1 - v1) / ((v1 + g1) - v1);
        float wz = (x2 - v2) / ((v2 + g2) - v2);

        unsigned b0 = (unsigned)(int)f0;
        unsigned b1 = (unsigned)(int)f1;
        unsigned b2 = (unsigned)(int)f2;

        unsigned hx0 = b0;                      // * PRIME0 (=1)
        unsigned hx1 = b0 + 1u;
        unsigned hy0 = b1 * PRIME1;
        unsigned hy1 = (b1 + 1u) * PRIME1;
        unsigned hz0 = b2 * PRIME2;
        unsigned hz1 = (b2 + 1u) * PRIME2;

        const float2* tb = emb + (size_t)l * TSIZE;

        // corner index c = i*4 + j*2 + k
        float2 e000 = __ldg(&tb[(hx0 ^ hy0 ^ hz0) & HMASK]);
        float2 e001 = __ldg(&tb[(hx0 ^ hy0 ^ hz1) & HMASK]);
        float2 e010 = __ldg(&tb[(hx0 ^ hy1 ^ hz0) & HMASK]);
        float2 e011 = __ldg(&tb[(hx0 ^ hy1 ^ hz1) & HMASK]);
        float2 e100 = __ldg(&tb[(hx1 ^ hy0 ^ hz0) & HMASK]);
        float2 e101 = __ldg(&tb[(hx1 ^ hy0 ^ hz1) & HMASK]);
        float2 e110 = __ldg(&tb[(hx1 ^ hy1 ^ hz0) & HMASK]);
        float2 e111 = __ldg(&tb[(hx1 ^ hy1 ^ hz1) & HMASK]);

        // trilinear: blend x, then y, then z (exact reference op order)
        float2 cx0 = lerp2(e000, e100, wx);
        float2 cx1 = lerp2(e001, e101, wx);
        float2 cx2 = lerp2(e010, e110, wx);
        float2 cx3 = lerp2(e011, e111, wx);
        float2 c0 = lerp2(cx0, cx2, wy);
        float2 c1 = lerp2(cx1, cx3, wy);
        float2 c  = lerp2(c0, c1, wz);

        float gate = sgate[l];
        o[2 * l + 0] = c.x * gate;
        o[2 * l + 1] = c.y * gate;
    }

    float4* o4 = reinterpret_cast<float4*>(out + (size_t)p * (2 * NLV));
#pragma unroll
    for (int q = 0; q < 8; q++)
        o4[q] = make_float4(o[4 * q + 0], o[4 * q + 1], o[4 * q + 2], o[4 * q + 3]);
}

extern "C" void kernel_launch(void* const* d_in, const int* in_sizes, int n_in,
                              void* d_out, int out_size) {
    const float*  x    = (const float*)d_in[0];
    const float2* emb  = (const float2*)d_in[1];
    const float*  lw   = (const float*)d_in[2];
    const float*  bmin = (const float*)d_in[3];
    const float*  bmax = (const float*)d_in[4];
    float* out = (float*)d_out;

    unsigned n = (unsigned)(in_sizes[0] / 3);
    unsigned t4 = (n + 3) / 4;

    void* cntPtr = nullptr;
    void* overPtr = nullptr;
    cudaGetSymbolAddress(&cntPtr, g_cnt);
    cudaGetSymbolAddress(&overPtr, g_over);
    cudaMemsetAsync(cntPtr, 0, BINS * sizeof(unsigned));
    cudaMemsetAsync(overPtr, 0, sizeof(unsigned));

    scatter_kernel<<<(t4 + 255) / 256, 256>>>(x, bmin, bmax, n);

    unsigned total = NSLOTS + OVMAX;
    hashenc_kernel<<<(total + 255) / 256, 256>>>(emb, lw, bmin, bmax, out);
}

// round 14
// speedup vs baseline: 3.2258x; 1.1210x over previous
#include <cuda_runtime.h>
#include <cstdint>

#define NLV 16
#define TSIZE (1u << 19)
#define HMASK (TSIZE - 1u)
#define PRIME1 2654435761u
#define PRIME2 805459861u

#define BINRES 32
#define BINS 32768                    // 32^3 Morton bins
#define NSLOTS 2097152u               // BINS * 64
#define OVMAX 65536u

__device__ unsigned g_cnt[BINS];
__device__ unsigned g_over[1];
__device__ float4   g_xs[2097152];    // bucketed points, xyz + orig index in w (32MB)
__device__ float4   g_xso[65536];     // overflow (1MB)

// floor(16 * b^i), b = exp((ln512 - ln16)/15) evaluated in float32 (numpy chain)
__device__ const float g_res[NLV] = {16.f, 20.f, 25.f, 32.f, 40.f, 50.f, 64.f, 80.f,
                                     101.f, 128.f, 161.f, 203.f, 256.f, 322.f, 406.f, 512.f};

static __device__ __forceinline__ float2 lerp2(float2 a, float2 b, float w) {
    float u = 1.0f - w;
    return make_float2(a.x * u + b.x * w, a.y * u + b.y * w);
}

// 5-bit 3D Morton expand: b4..b0 -> bits 12,9,6,3,0
static __device__ __forceinline__ unsigned expand_bits5(unsigned v) {
    v &= 0x1Fu;
    v = (v | (v << 8)) & 0x100Fu;
    v = (v | (v << 4)) & 0x10C3u;
    v = (v | (v << 2)) & 0x1249u;
    return v;
}

static __device__ __forceinline__ unsigned point_bin(float x0, float x1, float x2,
                                                     float bm0, float bm1, float bm2,
                                                     float bM0, float bM1, float bM2) {
    float u0 = (fminf(fmaxf(x0, bm0), bM0) - bm0) / (bM0 - bm0);
    float u1 = (fminf(fmaxf(x1, bm1), bM1) - bm1) / (bM1 - bm1);
    float u2 = (fminf(fmaxf(x2, bm2), bM2) - bm2) / (bM2 - bm2);
    unsigned i0 = min((unsigned)(u0 * (float)BINRES), (unsigned)(BINRES - 1));
    unsigned i1 = min((unsigned)(u1 * (float)BINRES), (unsigned)(BINRES - 1));
    unsigned i2 = min((unsigned)(u2 * (float)BINRES), (unsigned)(BINRES - 1));
    return expand_bits5(i0) | (expand_bits5(i1) << 1) | (expand_bits5(i2) << 2);
}

static __device__ __forceinline__ void load4pts(const float4* __restrict__ x4,
                                                unsigned t, float px[4][3]) {
    float4 a0 = __ldg(&x4[3 * (size_t)t + 0]);
    float4 a1 = __ldg(&x4[3 * (size_t)t + 1]);
    float4 a2 = __ldg(&x4[3 * (size_t)t + 2]);
    px[0][0] = a0.x; px[0][1] = a0.y; px[0][2] = a0.z;
    px[1][0] = a0.w; px[1][1] = a1.x; px[1][2] = a1.y;
    px[2][0] = a1.z; px[2][1] = a1.w; px[2][2] = a2.x;
    px[3][0] = a2.y; px[3][1] = a2.z; px[3][2] = a2.w;
}

static __device__ __forceinline__ void deposit(float q0, float q1, float q2,
                                               unsigned idx,
                                               float bm0, float bm1, float bm2,
                                               float bM0, float bM1, float bM2) {
    unsigned b = point_bin(q0, q1, q2, bm0, bm1, bm2, bM0, bM1, bM2);
    unsigned c = atomicAdd(&g_cnt[b], 1u);
    float4 v = make_float4(q0, q1, q2, __uint_as_float(idx));
    if (c < 64u) {
        g_xs[b * 64u + c] = v;
    } else {
        unsigned k = atomicAdd(&g_over[0], 1u);
        if (k < OVMAX) g_xso[k] = v;
    }
}

__global__ void __launch_bounds__(256)
scatter_kernel(const float* __restrict__ x,
               const float* __restrict__ bmin,
               const float* __restrict__ bmax, unsigned n) {
    unsigned t = blockIdx.x * blockDim.x + threadIdx.x;
    unsigned base = t * 4u;
    if (base >= n) return;
    float bm0 = __ldg(&bmin[0]), bm1 = __ldg(&bmin[1]), bm2 = __ldg(&bmin[2]);
    float bM0 = __ldg(&bmax[0]), bM1 = __ldg(&bmax[1]), bM2 = __ldg(&bmax[2]);
    if (base + 4 <= n) {
        float px[4][3];
        load4pts((const float4*)x, t, px);
#pragma unroll
        for (int k = 0; k < 4; k++)
            deposit(px[k][0], px[k][1], px[k][2], base + k,
                    bm0, bm1, bm2, bM0, bM1, bM2);
    } else {
        for (unsigned i = base; i < n; i++) {
            float q0 = __ldg(&x[3 * (size_t)i + 0]);
            float q1 = __ldg(&x[3 * (size_t)i + 1]);
            float q2 = __ldg(&x[3 * (size_t)i + 2]);
            deposit(q0, q1, q2, i, bm0, bm1, bm2, bM0, bM1, bM2);
        }
    }
}

// all 16 levels on bucketed (Morton-sorted) points; per-pair float4 stores
__global__ void __launch_bounds__(256)
hashenc_kernel(const float2* __restrict__ emb,   // [16][2^19] float2
               const float* __restrict__ lw,     // [16]
               const float* __restrict__ bmin,   // [3]
               const float* __restrict__ bmax,   // [3]
               float* __restrict__ out)          // [N, 32]
{
    // per-level constants, computed once per block
    __shared__ float sg0[NLV], sg1[NLV], sg2[NLV];       // grid components
    __shared__ float sr0[NLV], sr1[NLV], sr2[NLV];       // reciprocals (for floor)
    __shared__ float sgate[NLV];
    if (threadIdx.x < NLV) {
        int l = threadIdx.x;
        float res = g_res[l];
        float bm0 = __ldg(&bmin[0]), bm1 = __ldg(&bmin[1]), bm2 = __ldg(&bmin[2]);
        float bM0 = __ldg(&bmax[0]), bM1 = __ldg(&bmax[1]), bM2 = __ldg(&bmax[2]);
        float g0 = (bM0 - bm0) / res;
        float g1 = (bM1 - bm1) / res;
        float g2 = (bM2 - bm2) / res;
        sg0[l] = g0; sg1[l] = g1; sg2[l] = g2;
        sr0[l] = 1.0f / g0; sr1[l] = 1.0f / g1; sr2[l] = 1.0f / g2;
        sgate[l] = 1.0f / (1.0f + expf(-lw[l]));
    }
    __syncthreads();

    unsigned j = blockIdx.x * blockDim.x + threadIdx.x;

    float4 xp;
    if (j < NSLOTS) {
        unsigned bin = j >> 6;
        unsigned slot = j & 63u;
        unsigned cnt = g_cnt[bin];
        if (slot >= min(cnt, 64u)) return;
        xp = g_xs[j];
    } else {
        unsigned k = j - NSLOTS;
        if (k >= min(g_over[0], OVMAX)) return;
        xp = g_xso[k];
    }

    unsigned p = __float_as_uint(xp.w);   // original point index (output row)
    float x0 = xp.x, x1 = xp.y, x2 = xp.z;

    float bm0 = __ldg(&bmin[0]), bm1 = __ldg(&bmin[1]), bm2 = __ldg(&bmin[2]);
    float bM0 = __ldg(&bmax[0]), bM1 = __ldg(&bmax[1]), bM2 = __ldg(&bmax[2]);

    float xc0 = fminf(fmaxf(x0, bm0), bM0);
    float xc1 = fminf(fmaxf(x1, bm1), bM1);
    float xc2 = fminf(fmaxf(x2, bm2), bM2);

    float4* orow = reinterpret_cast<float4*>(out + (size_t)p * (2 * NLV));
    float pend0 = 0.f, pend1 = 0.f;      // even level's pair awaiting its partner

#pragma unroll
    for (int l = 0; l < NLV; l++) {
        float g0 = sg0[l], g1 = sg1[l], g2 = sg2[l];
        float f0 = floorf((xc0 - bm0) * sr0[l]);
        float f1 = floorf((xc1 - bm1) * sr1[l]);
        float f2 = floorf((xc2 - bm2) * sr2[l]);
        float v0 = f0 * g0 + bm0;
        float v1 = f1 * g1 + bm1;
        float v2 = f2 * g2 + bm2;
        // fast divide: <=2ulp, weights in [0,1] -> ~1e-7 output perturbation
        float wx = __fdividef(x0 - v0, (v0 + g0) - v0);
        float wy = __fdividef(x1 - v1, (v1 + g1) - v1);
        float wz = __fdividef(x2 - v2, (v2 + g2) - v2);

        unsigned b0 = (unsigned)(int)f0;
        unsigned b1 = (unsigned)(int)f1;
        unsigned b2 = (unsigned)(int)f2;

        unsigned hx0 = b0;                      // * PRIME0 (=1)
        unsigned hx1 = b0 + 1u;
        unsigned hy0 = b1 * PRIME1;
        unsigned hy1 = (b1 + 1u) * PRIME1;
        unsigned hz0 = b2 * PRIME2;
        unsigned hz1 = (b2 + 1u) * PRIME2;

        const float2* tb = emb + (size_t)l * TSIZE;

        // corner index c = i*4 + j*2 + k
        float2 e000 = __ldg(&tb[(hx0 ^ hy0 ^ hz0) & HMASK]);
        float2 e001 = __ldg(&tb[(hx0 ^ hy0 ^ hz1) & HMASK]);
        float2 e010 = __ldg(&tb[(hx0 ^ hy1 ^ hz0) & HMASK]);
        float2 e011 = __ldg(&tb[(hx0 ^ hy1 ^ hz1) & HMASK]);
        float2 e100 = __ldg(&tb[(hx1 ^ hy0 ^ hz0) & HMASK]);
        float2 e101 = __ldg(&tb[(hx1 ^ hy0 ^ hz1) & HMASK]);
        float2 e110 = __ldg(&tb[(hx1 ^ hy1 ^ hz0) & HMASK]);
        float2 e111 = __ldg(&tb[(hx1 ^ hy1 ^ hz1) & HMASK]);

        // trilinear: blend x, then y, then z (exact reference op order)
        float2 cx0 = lerp2(e000, e100, wx);
        float2 cx1 = lerp2(e001, e101, wx);
        float2 cx2 = lerp2(e010, e110, wx);
        float2 cx3 = lerp2(e011, e111, wx);
        float2 c0 = lerp2(cx0, cx2, wy);
        float2 c1 = lerp2(cx1, cx3, wy);
        float2 c  = lerp2(c0, c1, wz);

        float gate = sgate[l];
        float oa = c.x * gate;
        float ob = c.y * gate;

        if ((l & 1) == 0) {
            pend0 = oa; pend1 = ob;
        } else {
            // one aligned float4 per level pair: retire immediately
            orow[l >> 1] = make_float4(pend0, pend1, oa, ob);
        }
    }
}

extern "C" void kernel_launch(void* const* d_in, const int* in_sizes, int n_in,
                              void* d_out, int out_size) {
    const float*  x    = (const float*)d_in[0];
    const float2* emb  = (const float2*)d_in[1];
    const float*  lw   = (const float*)d_in[2];
    const float*  bmin = (const float*)d_in[3];
    const float*  bmax = (const float*)d_in[4];
    float* out = (float*)d_out;

    unsigned n = (unsigned)(in_sizes[0] / 3);
    unsigned t4 = (n + 3) / 4;

    void* cntPtr = nullptr;
    void* overPtr = nullptr;
    cudaGetSymbolAddress(&cntPtr, g_cnt);
    cudaGetSymbolAddress(&overPtr, g_over);
    cudaMemsetAsync(cntPtr, 0, BINS * sizeof(unsigned));
    cudaMemsetAsync(overPtr, 0, sizeof(unsigned));

    scatter_kernel<<<(t4 + 255) / 256, 256>>>(x, bmin, bmax, n);

    unsigned total = NSLOTS + OVMAX;
    hashenc_kernel<<<(total + 255) / 256, 256>>>(emb, lw, bmin, bmax, out);
}